// round 15
// baseline (speedup 1.0000x reference)
#include <cuda_runtime.h>
#include <cuda_bf16.h>
#include <cstdint>

// Problem constants
#define BB 2
#define TT 2048
#define QDIM 512
#define HH 8
#define DHH 64
#define WW 64
#define DM 512
#define NTOK (BB*TT)

// Split-bf16 GEMM constants: K' = 3*512 (hi|hi|lo vs hi|lo|hi)
#define GK 1536
#define KT 32
#define ROWB 80
#define ASTG (128*ROWB)
#define STGB (2*ASTG)
#define NSTG 3

// Scratch (static device globals; no allocs allowed)
__device__ float g_qkv[(size_t)NTOK * 1536];
__device__ float g_part[(size_t)2 * NTOK * DM];        // split-K partials (Wlin)
__device__ __nv_bfloat16 g_att[(size_t)NTOK * 3072];   // [qhi|qlo|chi|clo]
__device__ __nv_bfloat16 g_xs[(size_t)NTOK * GK];
__device__ __nv_bfloat16 g_ctxs[(size_t)NTOK * GK];
__device__ __nv_bfloat16 g_wqkv[(size_t)1536 * GK];
__device__ __nv_bfloat16 g_wlins[(size_t)DM * GK];

__device__ __forceinline__ uint32_t smem_u32(const void* p) {
    uint32_t a;
    asm("{ .reg .u64 t; cvta.to.shared.u64 t, %1; cvt.u32.u64 %0, t; }" : "=r"(a) : "l"(p));
    return a;
}

// pack two f32 into bf16x2 (first arg -> low half = first element in memory)
__device__ __forceinline__ uint32_t packbf2(float lo, float hi) {
    uint32_t d;
    asm("cvt.rn.bf16x2.f32 %0, %1, %2;" : "=r"(d) : "f"(hi), "f"(lo));
    return d;
}

__device__ __forceinline__ void ldsm4(uint32_t r[4], uint32_t addr) {
    asm volatile("ldmatrix.sync.aligned.m8n8.x4.shared.b16 {%0,%1,%2,%3}, [%4];"
                 : "=r"(r[0]), "=r"(r[1]), "=r"(r[2]), "=r"(r[3]) : "r"(addr));
}
__device__ __forceinline__ void ldsm4t(uint32_t r[4], uint32_t addr) {
    asm volatile("ldmatrix.sync.aligned.m8n8.x4.trans.shared.b16 {%0,%1,%2,%3}, [%4];"
                 : "=r"(r[0]), "=r"(r[1]), "=r"(r[2]), "=r"(r[3]) : "r"(addr));
}
__device__ __forceinline__ void mma16816(float c[4], const uint32_t a[4],
                                         uint32_t b0, uint32_t b1) {
    asm volatile(
        "mma.sync.aligned.m16n8k16.row.col.f32.bf16.bf16.f32 "
        "{%0,%1,%2,%3}, {%4,%5,%6,%7}, {%8,%9}, {%0,%1,%2,%3};"
        : "+f"(c[0]), "+f"(c[1]), "+f"(c[2]), "+f"(c[3])
        : "r"(a[0]), "r"(a[1]), "r"(a[2]), "r"(a[3]), "r"(b0), "r"(b1));
}
// cp.async with zfill when !ok (src-size 0 -> zero fill)
__device__ __forceinline__ void cp16(uint32_t dst, const void* src, bool ok) {
    const int sz = ok ? 16 : 0;
    asm volatile("cp.async.cg.shared.global [%0], [%1], 16, %2;"
                 :: "r"(dst), "l"(src), "r"(sz) : "memory");
}

// ---------------------------------------------------------------------------
// Fused split kernel (pre-GEMM conversions, one launch).
// A pattern: [hi | hi | lo].  B pattern: [hi | lo | hi].
// ---------------------------------------------------------------------------
#define NX (NTOK*512)
#define NQ (512*512)
#define NKV2 (1024*512)
#define NL (512*512)

__global__ void split_all(const float* __restrict__ x,
                          const float* __restrict__ Wq,
                          const float* __restrict__ Wkv,
                          const float* __restrict__ Wlin,
                          __nv_bfloat16* __restrict__ xs,
                          __nv_bfloat16* __restrict__ wqkv,
                          __nv_bfloat16* __restrict__ wlins)
{
    const int i = blockIdx.x * blockDim.x + threadIdx.x;
    float a;
    __nv_bfloat16* out;
    int r, c, bpat;
    if (i < NX) {
        a = x[i]; r = i >> 9; c = i & 511; out = xs; bpat = 0;
    } else if (i < NX + NQ) {
        const int j = i - NX;
        a = Wq[j]; r = j >> 9; c = j & 511; out = wqkv; bpat = 1;
    } else if (i < NX + NQ + NKV2) {
        const int j = i - NX - NQ;
        a = Wkv[j]; r = 512 + (j >> 9); c = j & 511; out = wqkv; bpat = 1;
    } else if (i < NX + NQ + NKV2 + NL) {
        const int j = i - NX - NQ - NKV2;
        a = Wlin[j]; r = j >> 9; c = j & 511; out = wlins; bpat = 1;
    } else return;

    const __nv_bfloat16 h = __float2bfloat16_rn(a);
    const __nv_bfloat16 l = __float2bfloat16_rn(a - __bfloat162float(h));
    const size_t base = (size_t)r * GK + c;
    out[base] = h;
    if (bpat) { out[base + 512] = l; out[base + 1024] = h; }
    else      { out[base + 512] = h; out[base + 1024] = l; }
}

// ---------------------------------------------------------------------------
// mma.sync bf16 GEMM: C = A'.B'^T (+bias), fp32 accum.
// Block 128x128, 256 threads, 3-stage cp.async pipeline, KT=32
// (measured-good config; unchanged).
// Split-K via blockIdx.z. Bias applied only when gridDim.z == 1.
// ---------------------------------------------------------------------------
__global__ __launch_bounds__(256, 2) void gemm_mma(
    const __nv_bfloat16* __restrict__ A,
    const __nv_bfloat16* __restrict__ B,
    float* __restrict__ C, int Ntot,
    const float* __restrict__ bias, int nkt)
{
    extern __shared__ char smem[];
    const uint32_t sbase = smem_u32(smem);

    const int tid  = threadIdx.x;
    const int lane = tid & 31;
    const int warp = tid >> 5;
    const int wm   = warp & 3;
    const int wn   = warp >> 2;
    const int m0   = blockIdx.y * 128;
    const int n0   = blockIdx.x * 128;
    const size_t koff = (size_t)blockIdx.z * nkt * KT;
    float* Cz = C + (size_t)blockIdx.z * NTOK * Ntot;

    const int ldRow = tid >> 2;
    const int ldJ   = tid & 3;
    const __nv_bfloat16* gA0 = A + (size_t)(m0 + ldRow) * GK + koff + ldJ * 8;
    const __nv_bfloat16* gA1 = A + (size_t)(m0 + ldRow + 64) * GK + koff + ldJ * 8;
    const __nv_bfloat16* gB0 = B + (size_t)(n0 + ldRow) * GK + koff + ldJ * 8;
    const __nv_bfloat16* gB1 = B + (size_t)(n0 + ldRow + 64) * GK + koff + ldJ * 8;
    const uint32_t sRow0 = ldRow * ROWB + ldJ * 16;
    const uint32_t sRow1 = (ldRow + 64) * ROWB + ldJ * 16;

    float c[2][8][4];
#pragma unroll
    for (int i = 0; i < 2; i++)
#pragma unroll
        for (int j = 0; j < 8; j++)
#pragma unroll
            for (int k = 0; k < 4; k++) c[i][j][k] = 0.f;

    auto issue = [&](int stage, int kt) {
        const uint32_t sa = sbase + stage * STGB;
        const uint32_t sb = sa + ASTG;
        const size_t ko = (size_t)kt * KT;
        asm volatile("cp.async.cg.shared.global [%0], [%1], 16;"
                     :: "r"(sa + sRow0), "l"(gA0 + ko) : "memory");
        asm volatile("cp.async.cg.shared.global [%0], [%1], 16;"
                     :: "r"(sa + sRow1), "l"(gA1 + ko) : "memory");
        asm volatile("cp.async.cg.shared.global [%0], [%1], 16;"
                     :: "r"(sb + sRow0), "l"(gB0 + ko) : "memory");
        asm volatile("cp.async.cg.shared.global [%0], [%1], 16;"
                     :: "r"(sb + sRow1), "l"(gB1 + ko) : "memory");
        asm volatile("cp.async.commit_group;" ::: "memory");
    };

    issue(0, 0);
    issue(1, 1);

    const uint32_t aRowOff = (uint32_t)(wm * 32 + (lane & 15)) * ROWB
                           + ((lane >> 4) << 4);
    const uint32_t bRowOff = (uint32_t)(wn * 64 + (lane & 7) + ((lane & 16) >> 1)) * ROWB
                           + ((lane & 8) << 1);

    for (int kt = 0; kt < nkt; kt++) {
        if (kt < nkt - 2) asm volatile("cp.async.wait_group 1;" ::: "memory");
        else              asm volatile("cp.async.wait_group 0;" ::: "memory");
        __syncthreads();

        const int stage = kt % NSTG;
        const uint32_t sa = sbase + stage * STGB;
        const uint32_t sb = sa + ASTG;

#pragma unroll
        for (int ks = 0; ks < 2; ks++) {
            uint32_t a[2][4];
#pragma unroll
            for (int mt = 0; mt < 2; mt++)
                ldsm4(a[mt], sa + aRowOff + mt * 16 * ROWB + ks * 32);
            uint32_t b[4][4];
#pragma unroll
            for (int p = 0; p < 4; p++)
                ldsm4(b[p], sb + bRowOff + p * 16 * ROWB + ks * 32);
#pragma unroll
            for (int mt = 0; mt < 2; mt++)
#pragma unroll
                for (int nt = 0; nt < 8; nt++) {
                    const int p = nt >> 1, q = (nt & 1) * 2;
                    mma16816(c[mt][nt], a[mt], b[p][q], b[p][q + 1]);
                }
        }

        if (kt + 2 < nkt) issue((kt + 2) % NSTG, kt + 2);
    }

#pragma unroll
    for (int mt = 0; mt < 2; mt++) {
        const int gm = m0 + wm * 32 + mt * 16 + (lane >> 2);
#pragma unroll
        for (int nt = 0; nt < 8; nt++) {
            const int gn = n0 + wn * 64 + nt * 8 + (lane & 3) * 2;
            float2 v0 = make_float2(c[mt][nt][0], c[mt][nt][1]);
            float2 v1 = make_float2(c[mt][nt][2], c[mt][nt][3]);
            if (bias) {
                const float b0 = bias[gn], b1 = bias[gn + 1];
                v0.x += b0; v0.y += b1;
                v1.x += b0; v1.y += b1;
            }
            *(float2*)&Cz[(size_t)gm * Ntot + gn]       = v0;
            *(float2*)&Cz[(size_t)(gm + 8) * Ntot + gn] = v1;
        }
    }
}

// ---------------------------------------------------------------------------
// Split-K combine: out = p0 + p1 + bias (per output column).
// ---------------------------------------------------------------------------
__global__ void combine_k(const float* __restrict__ part,
                          const float* __restrict__ bias,
                          float* __restrict__ out)
{
    const int i = (blockIdx.x * blockDim.x + threadIdx.x) * 4;
    if (i >= NTOK * DM) return;
    const float4 p0 = *(const float4*)(part + i);
    const float4 p1 = *(const float4*)(part + (size_t)NTOK * DM + i);
    const int col = i & 511;
    float4 r;
    r.x = p0.x + p1.x + bias[col];
    r.y = p0.y + p1.y + bias[col + 1];
    r.z = p0.z + p1.z + bias[col + 2];
    r.w = p0.w + p1.w + bias[col + 3];
    *(float4*)(out + i) = r;
}

// ---------------------------------------------------------------------------
// RoPE + split to bf16 planes. Input: qkv fp32 row [q|k_p|v_p] (1536).
// Output att row (3072 bf16): [qhi(512) | qlo(512) | chi(1024) | clo(1024)],
// where c = [rope(k_p) | v_p].
// ---------------------------------------------------------------------------
__global__ void rope_split(const float* __restrict__ qkv,
                           __nv_bfloat16* __restrict__ att)
{
    const int row = blockIdx.x;
    const int tid = threadIdx.x;
    const int t = row & (TT - 1);
    const float* pr = qkv + (size_t)row * 1536;
    __nv_bfloat16* po = att + (size_t)row * 3072;

    if (tid < 128) {
        float qy1[2], qy2[2], ky1[2], ky2[2];
#pragma unroll
        for (int e = 0; e < 2; e++) {
            const int c = 2 * tid + e;
            const float inv = powf(100.0f, -(float)c * (1.0f / 256.0f));
            const float ang = (float)t * inv;
            float s, co;
            sincosf(ang, &s, &co);
            float x1 = pr[c], x2 = pr[c + 256];
            qy1[e] = x1 * co - x2 * s;
            qy2[e] = x2 * co + x1 * s;
            x1 = pr[512 + c]; x2 = pr[512 + c + 256];
            ky1[e] = x1 * co - x2 * s;
            ky2[e] = x2 * co + x1 * s;
        }
        const int c0 = 2 * tid;
        {
            const float h0 = __bfloat162float(__float2bfloat16_rn(qy1[0]));
            const float h1 = __bfloat162float(__float2bfloat16_rn(qy1[1]));
            const float g0 = __bfloat162float(__float2bfloat16_rn(qy2[0]));
            const float g1 = __bfloat162float(__float2bfloat16_rn(qy2[1]));
            *(uint32_t*)(po + c0)             = packbf2(qy1[0], qy1[1]);
            *(uint32_t*)(po + c0 + 256)       = packbf2(qy2[0], qy2[1]);
            *(uint32_t*)(po + 512 + c0)       = packbf2(qy1[0] - h0, qy1[1] - h1);
            *(uint32_t*)(po + 512 + c0 + 256) = packbf2(qy2[0] - g0, qy2[1] - g1);
        }
        {
            const float h0 = __bfloat162float(__float2bfloat16_rn(ky1[0]));
            const float h1 = __bfloat162float(__float2bfloat16_rn(ky1[1]));
            const float g0 = __bfloat162float(__float2bfloat16_rn(ky2[0]));
            const float g1 = __bfloat162float(__float2bfloat16_rn(ky2[1]));
            *(uint32_t*)(po + 1024 + c0)       = packbf2(ky1[0], ky1[1]);
            *(uint32_t*)(po + 1024 + c0 + 256) = packbf2(ky2[0], ky2[1]);
            *(uint32_t*)(po + 2048 + c0)       = packbf2(ky1[0] - h0, ky1[1] - h1);
            *(uint32_t*)(po + 2048 + c0 + 256) = packbf2(ky2[0] - g0, ky2[1] - g1);
        }
    } else {
        const int c = 4 * (tid - 128);
        const float4 v = *(const float4*)(pr + 1024 + c);
        const float hx = __bfloat162float(__float2bfloat16_rn(v.x));
        const float hy = __bfloat162float(__float2bfloat16_rn(v.y));
        const float hz = __bfloat162float(__float2bfloat16_rn(v.z));
        const float hw = __bfloat162float(__float2bfloat16_rn(v.w));
        *(uint2*)(po + 1536 + c) = make_uint2(packbf2(v.x, v.y), packbf2(v.z, v.w));
        *(uint2*)(po + 2560 + c) = make_uint2(packbf2(v.x - hx, v.y - hy),
                                              packbf2(v.z - hz, v.w - hw));
    }
}

// ---------------------------------------------------------------------------
// MMA sliding-window sigmoid attention (band-restricted, pre-split operands).
// Per block: (b, h, 64 q rows), 128 threads (4 warps). Warp w: q rows
// [16w,16w+16), keys local r in [16w, 16w+80) (band w = r - qi in [0,64)).
// Q fragments are built directly from GLOBAL memory (L2-resident) — no Q
// smem planes. Smem holds only K/V hi/lo -> 72 KB -> 3 CTAs/SM.
// ---------------------------------------------------------------------------
#define AT_ROWB 144
#define SM_KHI 0
#define SM_KLO 18432
#define SM_VHI 36864
#define SM_VLO 55296
#define AT_SMEM 73728

__global__ __launch_bounds__(128, 3) void attn_mma(
    const __nv_bfloat16* __restrict__ att,
    const int* __restrict__ mask,
    __nv_bfloat16* __restrict__ ctxs)
{
    extern __shared__ char smem[];
    const uint32_t sb = smem_u32(smem);

    const int t0 = blockIdx.x * 64;
    const int h  = blockIdx.y;
    const int b  = blockIdx.z;
    const int tid  = threadIdx.x;
    const int lane = tid & 31;
    const int warp = tid >> 5;

    const __nv_bfloat16* gatt = att + (size_t)b * TT * 3072;

    // ---- cp.async prologue: K/V hi/lo only ----
    for (int i = tid; i < 4096; i += 128) {
        const int r = i >> 5, rem = i & 31;
        const int kv = rem >> 4, buf = (rem >> 3) & 1, ch = rem & 7;
        const int tk = t0 - 63 + r;
        const bool ok = (tk >= 0 && tk < TT);
        const int col = (buf ? 2048 : 1024) + h * 128 + kv * 64 + ch * 8;
        const __nv_bfloat16* src = gatt + (size_t)(ok ? tk : 0) * 3072 + col;
        const uint32_t base = kv ? (buf ? SM_VLO : SM_VHI) : (buf ? SM_KLO : SM_KHI);
        const uint32_t dst = sb + base + r * AT_ROWB + ch * 16;
        cp16(dst, src, ok);
    }
    asm volatile("cp.async.commit_group;" ::: "memory");

    // ---- Q fragment base pointers (global; rows qa, qb of this warp) ----
    const int m0 = warp * 16;
    const int qa = m0 + (lane >> 2);
    const int qb = qa + 8;
    const uint32_t* qAp = (const uint32_t*)(gatt + (size_t)(t0 + qa) * 3072 + h * 64);
    const uint32_t* qBp = (const uint32_t*)(gatt + (size_t)(t0 + qb) * 3072 + h * 64);
    // lo plane at +512 bf16 = +256 u32

    asm volatile("cp.async.wait_group 0;" ::: "memory");
    __syncthreads();

    // ---- QK^T: warp tile m16 x n80 (keys r in [m0, m0+80)), 3-term split ----
    const uint32_t bOff = (uint32_t)(m0 + (lane & 7) + ((lane & 16) >> 1)) * AT_ROWB
                        + ((lane & 8) << 1);

    float cs[10][4];
#pragma unroll
    for (int i = 0; i < 10; i++)
#pragma unroll
        for (int j = 0; j < 4; j++) cs[i][j] = 0.f;

#pragma unroll
    for (int ks = 0; ks < 4; ks++) {
        const int cc = ks * 8 + (lane & 3);
        const uint32_t ah[4] = { qAp[cc], qBp[cc], qAp[cc + 4], qBp[cc + 4] };
        const uint32_t al[4] = { qAp[256 + cc], qBp[256 + cc],
                                 qAp[256 + cc + 4], qBp[256 + cc + 4] };
#pragma unroll
        for (int ng = 0; ng < 5; ng++) {
            uint32_t bh[4], bl[4];
            ldsm4(bh, sb + SM_KHI + ng * (16 * AT_ROWB) + ks * 32 + bOff);
            mma16816(cs[2 * ng],     ah, bh[0], bh[1]);
            mma16816(cs[2 * ng + 1], ah, bh[2], bh[3]);
            mma16816(cs[2 * ng],     al, bh[0], bh[1]);
            mma16816(cs[2 * ng + 1], al, bh[2], bh[3]);
            ldsm4(bl, sb + SM_KLO + ng * (16 * AT_ROWB) + ks * 32 + bOff);
            mma16816(cs[2 * ng],     ah, bl[0], bl[1]);
            mma16816(cs[2 * ng + 1], ah, bl[2], bl[3]);
        }
    }

    // ---- sigmoid + band + mask in registers; split S to bf16 hi/lo ----
    const float SCALE = 0.125f;
    const float LOGW  = 4.1588830833596718f;
    const bool mka = mask[(size_t)b * TT + t0 + qa] != 0;
    const bool mkb = mask[(size_t)b * TT + t0 + qb] != 0;

    uint32_t SH[10][2], SL[10][2];
#pragma unroll
    for (int nt = 0; nt < 10; nt++) {
        const int r0 = m0 + nt * 8 + (lane & 3) * 2;
        float s[4];
#pragma unroll
        for (int e = 0; e < 2; e++) {
            const int r = r0 + e;
            {
                const int w = r - qa;
                float v = 0.f;
                if (w >= 0 && w < 64 && mka) {
                    const float val = cs[nt][e] * SCALE - LOGW;
                    v = 1.f / (1.f + __expf(-val));
                }
                s[e] = v;
            }
            {
                const int w = r - qb;
                float v = 0.f;
                if (w >= 0 && w < 64 && mkb) {
                    const float val = cs[nt][2 + e] * SCALE - LOGW;
                    v = 1.f / (1.f + __expf(-val));
                }
                s[2 + e] = v;
            }
        }
        const float h0 = __bfloat162float(__float2bfloat16_rn(s[0]));
        const float h1 = __bfloat162float(__float2bfloat16_rn(s[1]));
        const float h2 = __bfloat162float(__float2bfloat16_rn(s[2]));
        const float h3 = __bfloat162float(__float2bfloat16_rn(s[3]));
        SH[nt][0] = packbf2(s[0], s[1]);
        SH[nt][1] = packbf2(s[2], s[3]);
        SL[nt][0] = packbf2(s[0] - h0, s[1] - h1);
        SL[nt][1] = packbf2(s[2] - h2, s[3] - h3);
    }

    // ---- PV: C(16x64) = S(16x80) x V(80x64), V rows [m0, m0+80) ----
    float co[8][4];
#pragma unroll
    for (int i = 0; i < 8; i++)
#pragma unroll
        for (int j = 0; j < 4; j++) co[i][j] = 0.f;

    const uint32_t vOff = (uint32_t)((lane & 7) + (lane & 8)) * AT_ROWB
                        + ((lane & 16) >> 4) * 16;

#pragma unroll
    for (int ks = 0; ks < 5; ks++) {
        const uint32_t aH[4] = { SH[2*ks][0], SH[2*ks][1], SH[2*ks+1][0], SH[2*ks+1][1] };
        const uint32_t aL[4] = { SL[2*ks][0], SL[2*ks][1], SL[2*ks+1][0], SL[2*ks+1][1] };
        const uint32_t kOff = (uint32_t)(m0 + ks * 16) * AT_ROWB + vOff;
#pragma unroll
        for (int ng = 0; ng < 4; ng++) {
            uint32_t vh[4], vl[4];
            ldsm4t(vh, sb + SM_VHI + kOff + ng * 32);
            mma16816(co[2 * ng],     aH, vh[0], vh[1]);
            mma16816(co[2 * ng + 1], aH, vh[2], vh[3]);
            mma16816(co[2 * ng],     aL, vh[0], vh[1]);
            mma16816(co[2 * ng + 1], aL, vh[2], vh[3]);
            ldsm4t(vl, sb + SM_VLO + kOff + ng * 32);
            mma16816(co[2 * ng],     aH, vl[0], vl[1]);
            mma16816(co[2 * ng + 1], aH, vl[2], vl[3]);
        }
    }

    // ---- epilogue: write split-bf16 ctx (A pattern: hi, hi, lo) ----
    const size_t rowA = (size_t)(b * TT + t0 + qa) * GK + h * DHH;
    const size_t rowB = (size_t)(b * TT + t0 + qb) * GK + h * DHH;
#pragma unroll
    for (int nt = 0; nt < 8; nt++) {
        const int d = nt * 8 + (lane & 3) * 2;
        const float h0 = __bfloat162float(__float2bfloat16_rn(co[nt][0]));
        const float h1 = __bfloat162float(__float2bfloat16_rn(co[nt][1]));
        const float h2 = __bfloat162float(__float2bfloat16_rn(co[nt][2]));
        const float h3 = __bfloat162float(__float2bfloat16_rn(co[nt][3]));
        const uint32_t hA = packbf2(co[nt][0], co[nt][1]);
        const uint32_t lA = packbf2(co[nt][0] - h0, co[nt][1] - h1);
        const uint32_t hB = packbf2(co[nt][2], co[nt][3]);
        const uint32_t lB = packbf2(co[nt][2] - h2, co[nt][3] - h3);
        *(uint32_t*)(ctxs + rowA + d)        = hA;
        *(uint32_t*)(ctxs + rowA + 512 + d)  = hA;
        *(uint32_t*)(ctxs + rowA + 1024 + d) = lA;
        *(uint32_t*)(ctxs + rowB + d)        = hB;
        *(uint32_t*)(ctxs + rowB + 512 + d)  = hB;
        *(uint32_t*)(ctxs + rowB + 1024 + d) = lB;
    }
}

// ---------------------------------------------------------------------------
// Launch
// ---------------------------------------------------------------------------
extern "C" void kernel_launch(void* const* d_in, const int* in_sizes, int n_in,
                              void* d_out, int out_size)
{
    const float* x    = (const float*)d_in[0];
    const int* mk     = (const int*)d_in[1];     // bool delivered as int32
    const float* Wq   = (const float*)d_in[2];
    const float* Wkv  = (const float*)d_in[3];
    const float* Wlin = (const float*)d_in[4];
    const float* blin = (const float*)d_in[5];
    float* out        = (float*)d_out;

    void *pqkv, *ppart, *patt, *pxs, *pctxs, *pwqkv, *pwlins;
    cudaGetSymbolAddress(&pqkv, g_qkv);
    cudaGetSymbolAddress(&ppart, g_part);
    cudaGetSymbolAddress(&patt, g_att);
    cudaGetSymbolAddress(&pxs, g_xs);
    cudaGetSymbolAddress(&pctxs, g_ctxs);
    cudaGetSymbolAddress(&pwqkv, g_wqkv);
    cudaGetSymbolAddress(&pwlins, g_wlins);
    float* qkv  = (float*)pqkv;
    float* part = (float*)ppart;
    __nv_bfloat16* att   = (__nv_bfloat16*)patt;
    __nv_bfloat16* xs    = (__nv_bfloat16*)pxs;
    __nv_bfloat16* ctxs  = (__nv_bfloat16*)pctxs;
    __nv_bfloat16* wqkv  = (__nv_bfloat16*)pwqkv;
    __nv_bfloat16* wlins = (__nv_bfloat16*)pwlins;

    const int gemm_smem = NSTG * STGB;   // 61440
    cudaFuncSetAttribute(gemm_mma, cudaFuncAttributeMaxDynamicSharedMemorySize, gemm_smem);
    cudaFuncSetAttribute(attn_mma, cudaFuncAttributeMaxDynamicSharedMemorySize, AT_SMEM);

    // one fused split for all pre-GEMM conversions
    {
        const int total = NX + NQ + NKV2 + NL;
        split_all<<<(total + 255) / 256, 256>>>(x, Wq, Wkv, Wlin, xs, wqkv, wlins);
    }

    // fused Q+KV projection: 4096 x 1536 (full K, gridDim.z = 1, 48 k-tiles)
    {
        dim3 grid(1536 / 128, NTOK / 128, 1);
        gemm_mma<<<grid, 256, gemm_smem>>>(xs, wqkv, qkv, 1536, nullptr, GK / KT);
    }
    // RoPE + split to bf16 planes
    rope_split<<<NTOK, 256>>>(qkv, att);

    // MMA attention (band-restricted, pre-split operands, 3 CTAs/SM)
    {
        dim3 grid(TT / 64, HH, BB);
        attn_mma<<<grid, 128, AT_SMEM>>>(att, mk, ctxs);
    }

    // output projection: split-K = 2 into partials (24 k-tiles each), combine
    {
        dim3 grid(DM / 128, NTOK / 128, 2);
        gemm_mma<<<grid, 256, gemm_smem>>>(ctxs, wlins, part, DM, nullptr, GK / KT / 2);
        combine_k<<<(NTOK * DM / 4 + 255) / 256, 256>>>(part, blin, out);
    }
}

// round 16
// speedup vs baseline: 1.0215x; 1.0215x over previous
#include <cuda_runtime.h>
#include <cuda_bf16.h>
#include <cstdint>

// Problem constants
#define BB 2
#define TT 2048
#define QDIM 512
#define HH 8
#define DHH 64
#define WW 64
#define DM 512
#define NTOK (BB*TT)

// Split-bf16 GEMM constants: K' = 3*512 (hi|hi|lo vs hi|lo|hi)
#define GK 1536
#define KT 32
#define ROWB 80
#define ASTG (128*ROWB)
#define STGB (2*ASTG)
#define NSTG 3

// Scratch (static device globals; no allocs allowed)
__device__ float g_qkv[(size_t)NTOK * 1536];
__device__ float g_part[(size_t)2 * NTOK * DM];        // split-K partials (Wlin)
__device__ __nv_bfloat16 g_att[(size_t)NTOK * 3072];   // [qhi|qlo|chi|clo]
__device__ __nv_bfloat16 g_xs[(size_t)NTOK * GK];
__device__ __nv_bfloat16 g_ctxs[(size_t)NTOK * GK];
__device__ __nv_bfloat16 g_wqkv[(size_t)1536 * GK];
__device__ __nv_bfloat16 g_wlins[(size_t)DM * GK];

__device__ __forceinline__ uint32_t smem_u32(const void* p) {
    uint32_t a;
    asm("{ .reg .u64 t; cvta.to.shared.u64 t, %1; cvt.u32.u64 %0, t; }" : "=r"(a) : "l"(p));
    return a;
}

// pack two f32 into bf16x2 (first arg -> low half = first element in memory)
__device__ __forceinline__ uint32_t packbf2(float lo, float hi) {
    uint32_t d;
    asm("cvt.rn.bf16x2.f32 %0, %1, %2;" : "=r"(d) : "f"(hi), "f"(lo));
    return d;
}

__device__ __forceinline__ void ldsm4(uint32_t r[4], uint32_t addr) {
    asm volatile("ldmatrix.sync.aligned.m8n8.x4.shared.b16 {%0,%1,%2,%3}, [%4];"
                 : "=r"(r[0]), "=r"(r[1]), "=r"(r[2]), "=r"(r[3]) : "r"(addr));
}
__device__ __forceinline__ void ldsm4t(uint32_t r[4], uint32_t addr) {
    asm volatile("ldmatrix.sync.aligned.m8n8.x4.trans.shared.b16 {%0,%1,%2,%3}, [%4];"
                 : "=r"(r[0]), "=r"(r[1]), "=r"(r[2]), "=r"(r[3]) : "r"(addr));
}
__device__ __forceinline__ void mma16816(float c[4], const uint32_t a[4],
                                         uint32_t b0, uint32_t b1) {
    asm volatile(
        "mma.sync.aligned.m16n8k16.row.col.f32.bf16.bf16.f32 "
        "{%0,%1,%2,%3}, {%4,%5,%6,%7}, {%8,%9}, {%0,%1,%2,%3};"
        : "+f"(c[0]), "+f"(c[1]), "+f"(c[2]), "+f"(c[3])
        : "r"(a[0]), "r"(a[1]), "r"(a[2]), "r"(a[3]), "r"(b0), "r"(b1));
}
// cp.async with zfill when !ok (src-size 0 -> zero fill)
__device__ __forceinline__ void cp16(uint32_t dst, const void* src, bool ok) {
    const int sz = ok ? 16 : 0;
    asm volatile("cp.async.cg.shared.global [%0], [%1], 16, %2;"
                 :: "r"(dst), "l"(src), "r"(sz) : "memory");
}

// ---------------------------------------------------------------------------
// Fused split kernel (pre-GEMM conversions, one launch).
// A pattern: [hi | hi | lo].  B pattern: [hi | lo | hi].
// ---------------------------------------------------------------------------
#define NX (NTOK*512)
#define NQ (512*512)
#define NKV2 (1024*512)
#define NL (512*512)

__global__ void split_all(const float* __restrict__ x,
                          const float* __restrict__ Wq,
                          const float* __restrict__ Wkv,
                          const float* __restrict__ Wlin,
                          __nv_bfloat16* __restrict__ xs,
                          __nv_bfloat16* __restrict__ wqkv,
                          __nv_bfloat16* __restrict__ wlins)
{
    const int i = blockIdx.x * blockDim.x + threadIdx.x;
    float a;
    __nv_bfloat16* out;
    int r, c, bpat;
    if (i < NX) {
        a = x[i]; r = i >> 9; c = i & 511; out = xs; bpat = 0;
    } else if (i < NX + NQ) {
        const int j = i - NX;
        a = Wq[j]; r = j >> 9; c = j & 511; out = wqkv; bpat = 1;
    } else if (i < NX + NQ + NKV2) {
        const int j = i - NX - NQ;
        a = Wkv[j]; r = 512 + (j >> 9); c = j & 511; out = wqkv; bpat = 1;
    } else if (i < NX + NQ + NKV2 + NL) {
        const int j = i - NX - NQ - NKV2;
        a = Wlin[j]; r = j >> 9; c = j & 511; out = wlins; bpat = 1;
    } else return;

    const __nv_bfloat16 h = __float2bfloat16_rn(a);
    const __nv_bfloat16 l = __float2bfloat16_rn(a - __bfloat162float(h));
    const size_t base = (size_t)r * GK + c;
    out[base] = h;
    if (bpat) { out[base + 512] = l; out[base + 1024] = h; }
    else      { out[base + 512] = h; out[base + 1024] = l; }
}

// ---------------------------------------------------------------------------
// mma.sync bf16 GEMM: C = A'.B'^T (+bias), fp32 accum.
// Block 128x128, 256 threads, 3-stage cp.async pipeline, KT=32
// (measured-good config; unchanged).
// Split-K via blockIdx.z. Bias applied only when gridDim.z == 1.
// ---------------------------------------------------------------------------
__global__ __launch_bounds__(256, 2) void gemm_mma(
    const __nv_bfloat16* __restrict__ A,
    const __nv_bfloat16* __restrict__ B,
    float* __restrict__ C, int Ntot,
    const float* __restrict__ bias, int nkt)
{
    extern __shared__ char smem[];
    const uint32_t sbase = smem_u32(smem);

    const int tid  = threadIdx.x;
    const int lane = tid & 31;
    const int warp = tid >> 5;
    const int wm   = warp & 3;
    const int wn   = warp >> 2;
    const int m0   = blockIdx.y * 128;
    const int n0   = blockIdx.x * 128;
    const size_t koff = (size_t)blockIdx.z * nkt * KT;
    float* Cz = C + (size_t)blockIdx.z * NTOK * Ntot;

    const int ldRow = tid >> 2;
    const int ldJ   = tid & 3;
    const __nv_bfloat16* gA0 = A + (size_t)(m0 + ldRow) * GK + koff + ldJ * 8;
    const __nv_bfloat16* gA1 = A + (size_t)(m0 + ldRow + 64) * GK + koff + ldJ * 8;
    const __nv_bfloat16* gB0 = B + (size_t)(n0 + ldRow) * GK + koff + ldJ * 8;
    const __nv_bfloat16* gB1 = B + (size_t)(n0 + ldRow + 64) * GK + koff + ldJ * 8;
    const uint32_t sRow0 = ldRow * ROWB + ldJ * 16;
    const uint32_t sRow1 = (ldRow + 64) * ROWB + ldJ * 16;

    float c[2][8][4];
#pragma unroll
    for (int i = 0; i < 2; i++)
#pragma unroll
        for (int j = 0; j < 8; j++)
#pragma unroll
            for (int k = 0; k < 4; k++) c[i][j][k] = 0.f;

    auto issue = [&](int stage, int kt) {
        const uint32_t sa = sbase + stage * STGB;
        const uint32_t sb = sa + ASTG;
        const size_t ko = (size_t)kt * KT;
        asm volatile("cp.async.cg.shared.global [%0], [%1], 16;"
                     :: "r"(sa + sRow0), "l"(gA0 + ko) : "memory");
        asm volatile("cp.async.cg.shared.global [%0], [%1], 16;"
                     :: "r"(sa + sRow1), "l"(gA1 + ko) : "memory");
        asm volatile("cp.async.cg.shared.global [%0], [%1], 16;"
                     :: "r"(sb + sRow0), "l"(gB0 + ko) : "memory");
        asm volatile("cp.async.cg.shared.global [%0], [%1], 16;"
                     :: "r"(sb + sRow1), "l"(gB1 + ko) : "memory");
        asm volatile("cp.async.commit_group;" ::: "memory");
    };

    issue(0, 0);
    issue(1, 1);

    const uint32_t aRowOff = (uint32_t)(wm * 32 + (lane & 15)) * ROWB
                           + ((lane >> 4) << 4);
    const uint32_t bRowOff = (uint32_t)(wn * 64 + (lane & 7) + ((lane & 16) >> 1)) * ROWB
                           + ((lane & 8) << 1);

    for (int kt = 0; kt < nkt; kt++) {
        if (kt < nkt - 2) asm volatile("cp.async.wait_group 1;" ::: "memory");
        else              asm volatile("cp.async.wait_group 0;" ::: "memory");
        __syncthreads();

        const int stage = kt % NSTG;
        const uint32_t sa = sbase + stage * STGB;
        const uint32_t sb = sa + ASTG;

#pragma unroll
        for (int ks = 0; ks < 2; ks++) {
            uint32_t a[2][4];
#pragma unroll
            for (int mt = 0; mt < 2; mt++)
                ldsm4(a[mt], sa + aRowOff + mt * 16 * ROWB + ks * 32);
            uint32_t b[4][4];
#pragma unroll
            for (int p = 0; p < 4; p++)
                ldsm4(b[p], sb + bRowOff + p * 16 * ROWB + ks * 32);
#pragma unroll
            for (int mt = 0; mt < 2; mt++)
#pragma unroll
                for (int nt = 0; nt < 8; nt++) {
                    const int p = nt >> 1, q = (nt & 1) * 2;
                    mma16816(c[mt][nt], a[mt], b[p][q], b[p][q + 1]);
                }
        }

        if (kt + 2 < nkt) issue((kt + 2) % NSTG, kt + 2);
    }

#pragma unroll
    for (int mt = 0; mt < 2; mt++) {
        const int gm = m0 + wm * 32 + mt * 16 + (lane >> 2);
#pragma unroll
        for (int nt = 0; nt < 8; nt++) {
            const int gn = n0 + wn * 64 + nt * 8 + (lane & 3) * 2;
            float2 v0 = make_float2(c[mt][nt][0], c[mt][nt][1]);
            float2 v1 = make_float2(c[mt][nt][2], c[mt][nt][3]);
            if (bias) {
                const float b0 = bias[gn], b1 = bias[gn + 1];
                v0.x += b0; v0.y += b1;
                v1.x += b0; v1.y += b1;
            }
            *(float2*)&Cz[(size_t)gm * Ntot + gn]       = v0;
            *(float2*)&Cz[(size_t)(gm + 8) * Ntot + gn] = v1;
        }
    }
}

// ---------------------------------------------------------------------------
// Split-K combine: out = p0 + p1 + bias (per output column).
// ---------------------------------------------------------------------------
__global__ void combine_k(const float* __restrict__ part,
                          const float* __restrict__ bias,
                          float* __restrict__ out)
{
    const int i = (blockIdx.x * blockDim.x + threadIdx.x) * 4;
    if (i >= NTOK * DM) return;
    const float4 p0 = *(const float4*)(part + i);
    const float4 p1 = *(const float4*)(part + (size_t)NTOK * DM + i);
    const int col = i & 511;
    float4 r;
    r.x = p0.x + p1.x + bias[col];
    r.y = p0.y + p1.y + bias[col + 1];
    r.z = p0.z + p1.z + bias[col + 2];
    r.w = p0.w + p1.w + bias[col + 3];
    *(float4*)(out + i) = r;
}

// ---------------------------------------------------------------------------
// RoPE + split to bf16 planes. Input: qkv fp32 row [q|k_p|v_p] (1536).
// Output att row (3072 bf16): [qhi(512) | qlo(512) | chi(1024) | clo(1024)],
// where c = [rope(k_p) | v_p].
// ---------------------------------------------------------------------------
__global__ void rope_split(const float* __restrict__ qkv,
                           __nv_bfloat16* __restrict__ att)
{
    const int row = blockIdx.x;
    const int tid = threadIdx.x;
    const int t = row & (TT - 1);
    const float* pr = qkv + (size_t)row * 1536;
    __nv_bfloat16* po = att + (size_t)row * 3072;

    if (tid < 128) {
        float qy1[2], qy2[2], ky1[2], ky2[2];
#pragma unroll
        for (int e = 0; e < 2; e++) {
            const int c = 2 * tid + e;
            const float inv = powf(100.0f, -(float)c * (1.0f / 256.0f));
            const float ang = (float)t * inv;
            float s, co;
            sincosf(ang, &s, &co);
            float x1 = pr[c], x2 = pr[c + 256];
            qy1[e] = x1 * co - x2 * s;
            qy2[e] = x2 * co + x1 * s;
            x1 = pr[512 + c]; x2 = pr[512 + c + 256];
            ky1[e] = x1 * co - x2 * s;
            ky2[e] = x2 * co + x1 * s;
        }
        const int c0 = 2 * tid;
        {
            const float h0 = __bfloat162float(__float2bfloat16_rn(qy1[0]));
            const float h1 = __bfloat162float(__float2bfloat16_rn(qy1[1]));
            const float g0 = __bfloat162float(__float2bfloat16_rn(qy2[0]));
            const float g1 = __bfloat162float(__float2bfloat16_rn(qy2[1]));
            *(uint32_t*)(po + c0)             = packbf2(qy1[0], qy1[1]);
            *(uint32_t*)(po + c0 + 256)       = packbf2(qy2[0], qy2[1]);
            *(uint32_t*)(po + 512 + c0)       = packbf2(qy1[0] - h0, qy1[1] - h1);
            *(uint32_t*)(po + 512 + c0 + 256) = packbf2(qy2[0] - g0, qy2[1] - g1);
        }
        {
            const float h0 = __bfloat162float(__float2bfloat16_rn(ky1[0]));
            const float h1 = __bfloat162float(__float2bfloat16_rn(ky1[1]));
            const float g0 = __bfloat162float(__float2bfloat16_rn(ky2[0]));
            const float g1 = __bfloat162float(__float2bfloat16_rn(ky2[1]));
            *(uint32_t*)(po + 1024 + c0)       = packbf2(ky1[0], ky1[1]);
            *(uint32_t*)(po + 1024 + c0 + 256) = packbf2(ky2[0], ky2[1]);
            *(uint32_t*)(po + 2048 + c0)       = packbf2(ky1[0] - h0, ky1[1] - h1);
            *(uint32_t*)(po + 2048 + c0 + 256) = packbf2(ky2[0] - g0, ky2[1] - g1);
        }
    } else {
        const int c = 4 * (tid - 128);
        const float4 v = *(const float4*)(pr + 1024 + c);
        const float hx = __bfloat162float(__float2bfloat16_rn(v.x));
        const float hy = __bfloat162float(__float2bfloat16_rn(v.y));
        const float hz = __bfloat162float(__float2bfloat16_rn(v.z));
        const float hw = __bfloat162float(__float2bfloat16_rn(v.w));
        *(uint2*)(po + 1536 + c) = make_uint2(packbf2(v.x, v.y), packbf2(v.z, v.w));
        *(uint2*)(po + 2560 + c) = make_uint2(packbf2(v.x - hx, v.y - hy),
                                              packbf2(v.z - hz, v.w - hw));
    }
}

// ---------------------------------------------------------------------------
// MMA sliding-window sigmoid attention, split-band version.
// Per block: (b, h, 64 q rows), 256 threads (8 warps). Warp pair p owns q
// rows [16p, 16p+16); sub-warp 0 handles key groups ng 0..2 (keys
// [m0, m0+48)), sub-warp 1 handles ng 3..4 (keys [m0+48, m0+80)).
// Sub-warp 1 writes its PV partial to smem; sub-warp 0 adds + epilogue.
// ---------------------------------------------------------------------------
#define AT_ROWB 144
#define SM_QHI 0
#define SM_QLO 9216
#define SM_KHI 18432
#define SM_KLO 36864
#define SM_VHI 55296
#define SM_VLO 73728
#define SM_RED 92160
#define AT_SMEM 108544

__global__ __launch_bounds__(256, 2) void attn_mma(
    const __nv_bfloat16* __restrict__ att,
    const int* __restrict__ mask,
    __nv_bfloat16* __restrict__ ctxs)
{
    extern __shared__ char smem[];
    const uint32_t sb = smem_u32(smem);

    const int t0 = blockIdx.x * 64;
    const int h  = blockIdx.y;
    const int b  = blockIdx.z;
    const int tid  = threadIdx.x;
    const int lane = tid & 31;
    const int warp = tid >> 5;          // 0..7
    const int p    = warp >> 1;         // q-row pair 0..3
    const int sub  = warp & 1;          // band half

    const __nv_bfloat16* gatt = att + (size_t)b * TT * 3072;

    // ---- cp.async prologue (256 threads) ----
    for (int i = tid; i < 1024; i += 256) {
        const int r = i >> 4, rem = i & 15;
        const int buf = rem >> 3, ch = rem & 7;
        const __nv_bfloat16* src = gatt + (size_t)(t0 + r) * 3072
                                 + buf * 512 + h * 64 + ch * 8;
        const uint32_t dst = sb + (buf ? SM_QLO : SM_QHI) + r * AT_ROWB + ch * 16;
        cp16(dst, src, true);
    }
    for (int i = tid; i < 4096; i += 256) {
        const int r = i >> 5, rem = i & 31;
        const int kv = rem >> 4, buf = (rem >> 3) & 1, ch = rem & 7;
        const int tk = t0 - 63 + r;
        const bool ok = (tk >= 0 && tk < TT);
        const int col = (buf ? 2048 : 1024) + h * 128 + kv * 64 + ch * 8;
        const __nv_bfloat16* src = gatt + (size_t)(ok ? tk : 0) * 3072 + col;
        const uint32_t base = kv ? (buf ? SM_VLO : SM_VHI) : (buf ? SM_KLO : SM_KHI);
        const uint32_t dst = sb + base + r * AT_ROWB + ch * 16;
        cp16(dst, src, ok);
    }
    asm volatile("cp.async.commit_group;" ::: "memory");
    asm volatile("cp.async.wait_group 0;" ::: "memory");
    __syncthreads();

    // ---- QK^T: warp handles m16 x (sub? 32 : 48) keys, 3-term split ----
    const int m0 = p * 16;
    const int ngBase = sub ? 3 : 0;
    const int ngCnt  = sub ? 2 : 3;
    const uint32_t aOff = (uint32_t)(m0 + (lane & 15)) * AT_ROWB + ((lane >> 4) << 4);
    const uint32_t bOff = (uint32_t)(m0 + (lane & 7) + ((lane & 16) >> 1)) * AT_ROWB
                        + ((lane & 8) << 1);

    float cs[6][4];
#pragma unroll
    for (int i = 0; i < 6; i++)
#pragma unroll
        for (int j = 0; j < 4; j++) cs[i][j] = 0.f;

#pragma unroll
    for (int ks = 0; ks < 4; ks++) {
        uint32_t ah[4], al[4];
        ldsm4(ah, sb + SM_QHI + aOff + ks * 32);
        ldsm4(al, sb + SM_QLO + aOff + ks * 32);
#pragma unroll
        for (int g = 0; g < 3; g++) {
            if (g >= ngCnt) break;
            const int ng = ngBase + g;
            uint32_t bh[4], bl[4];
            ldsm4(bh, sb + SM_KHI + ng * (16 * AT_ROWB) + ks * 32 + bOff);
            mma16816(cs[2 * g],     ah, bh[0], bh[1]);
            mma16816(cs[2 * g + 1], ah, bh[2], bh[3]);
            mma16816(cs[2 * g],     al, bh[0], bh[1]);
            mma16816(cs[2 * g + 1], al, bh[2], bh[3]);
            ldsm4(bl, sb + SM_KLO + ng * (16 * AT_ROWB) + ks * 32 + bOff);
            mma16816(cs[2 * g],     ah, bl[0], bl[1]);
            mma16816(cs[2 * g + 1], ah, bl[2], bl[3]);
        }
    }

    // ---- sigmoid + band + mask; split S to bf16 hi/lo (own key range) ----
    const float SCALE = 0.125f;
    const float LOGW  = 4.1588830833596718f;
    const int qa = m0 + (lane >> 2);
    const int qb = qa + 8;
    const bool mka = mask[(size_t)b * TT + t0 + qa] != 0;
    const bool mkb = mask[(size_t)b * TT + t0 + qb] != 0;

    uint32_t SH[6][2], SL[6][2];
#pragma unroll
    for (int l = 0; l < 6; l++) {
        if (l >= 2 * ngCnt) break;
        const int gnt = 2 * ngBase + l;                 // global n8-group
        const int r0 = m0 + gnt * 8 + (lane & 3) * 2;
        float s[4];
#pragma unroll
        for (int e = 0; e < 2; e++) {
            const int r = r0 + e;
            {
                const int w = r - qa;
                float v = 0.f;
                if (w >= 0 && w < 64 && mka) {
                    const float val = cs[l][e] * SCALE - LOGW;
                    v = 1.f / (1.f + __expf(-val));
                }
                s[e] = v;
            }
            {
                const int w = r - qb;
                float v = 0.f;
                if (w >= 0 && w < 64 && mkb) {
                    const float val = cs[l][2 + e] * SCALE - LOGW;
                    v = 1.f / (1.f + __expf(-val));
                }
                s[2 + e] = v;
            }
        }
        const float h0 = __bfloat162float(__float2bfloat16_rn(s[0]));
        const float h1 = __bfloat162float(__float2bfloat16_rn(s[1]));
        const float h2 = __bfloat162float(__float2bfloat16_rn(s[2]));
        const float h3 = __bfloat162float(__float2bfloat16_rn(s[3]));
        SH[l][0] = packbf2(s[0], s[1]);
        SH[l][1] = packbf2(s[2], s[3]);
        SL[l][0] = packbf2(s[0] - h0, s[1] - h1);
        SL[l][1] = packbf2(s[2] - h2, s[3] - h3);
    }

    // ---- PV partial: C(16x64) = S(16x{48|32}) x V(own key rows) ----
    float co[8][4];
#pragma unroll
    for (int i = 0; i < 8; i++)
#pragma unroll
        for (int j = 0; j < 4; j++) co[i][j] = 0.f;

    const uint32_t vOff = (uint32_t)((lane & 7) + (lane & 8)) * AT_ROWB
                        + ((lane & 16) >> 4) * 16;

#pragma unroll
    for (int g = 0; g < 3; g++) {
        if (g >= ngCnt) break;
        const int ksG = ngBase + g;
        const uint32_t aH[4] = { SH[2*g][0], SH[2*g][1], SH[2*g+1][0], SH[2*g+1][1] };
        const uint32_t aL[4] = { SL[2*g][0], SL[2*g][1], SL[2*g+1][0], SL[2*g+1][1] };
        const uint32_t kOff = (uint32_t)(m0 + ksG * 16) * AT_ROWB + vOff;
#pragma unroll
        for (int ng2 = 0; ng2 < 4; ng2++) {
            uint32_t vh[4], vl[4];
            ldsm4t(vh, sb + SM_VHI + kOff + ng2 * 32);
            mma16816(co[2 * ng2],     aH, vh[0], vh[1]);
            mma16816(co[2 * ng2 + 1], aH, vh[2], vh[3]);
            mma16816(co[2 * ng2],     aL, vh[0], vh[1]);
            mma16816(co[2 * ng2 + 1], aL, vh[2], vh[3]);
            ldsm4t(vl, sb + SM_VLO + kOff + ng2 * 32);
            mma16816(co[2 * ng2],     aH, vl[0], vl[1]);
            mma16816(co[2 * ng2 + 1], aH, vl[2], vl[3]);
        }
    }

    // ---- pair reduction: sub 1 writes partial, sub 0 adds + epilogue ----
    float* red = (float*)(smem + SM_RED + p * 4096);
    if (sub == 1) {
#pragma unroll
        for (int nt = 0; nt < 8; nt++)
            *(float4*)(red + nt * 128 + lane * 4) =
                make_float4(co[nt][0], co[nt][1], co[nt][2], co[nt][3]);
    }
    __syncthreads();
    if (sub == 0) {
#pragma unroll
        for (int nt = 0; nt < 8; nt++) {
            const float4 r = *(const float4*)(red + nt * 128 + lane * 4);
            co[nt][0] += r.x; co[nt][1] += r.y;
            co[nt][2] += r.z; co[nt][3] += r.w;
        }

        const size_t rowA = (size_t)(b * TT + t0 + qa) * GK + h * DHH;
        const size_t rowB = (size_t)(b * TT + t0 + qb) * GK + h * DHH;
#pragma unroll
        for (int nt = 0; nt < 8; nt++) {
            const int d = nt * 8 + (lane & 3) * 2;
            const float h0 = __bfloat162float(__float2bfloat16_rn(co[nt][0]));
            const float h1 = __bfloat162float(__float2bfloat16_rn(co[nt][1]));
            const float h2 = __bfloat162float(__float2bfloat16_rn(co[nt][2]));
            const float h3 = __bfloat162float(__float2bfloat16_rn(co[nt][3]));
            const uint32_t hA = packbf2(co[nt][0], co[nt][1]);
            const uint32_t lA = packbf2(co[nt][0] - h0, co[nt][1] - h1);
            const uint32_t hB = packbf2(co[nt][2], co[nt][3]);
            const uint32_t lB = packbf2(co[nt][2] - h2, co[nt][3] - h3);
            *(uint32_t*)(ctxs + rowA + d)        = hA;
            *(uint32_t*)(ctxs + rowA + 512 + d)  = hA;
            *(uint32_t*)(ctxs + rowA + 1024 + d) = lA;
            *(uint32_t*)(ctxs + rowB + d)        = hB;
            *(uint32_t*)(ctxs + rowB + 512 + d)  = hB;
            *(uint32_t*)(ctxs + rowB + 1024 + d) = lB;
        }
    }
}

// ---------------------------------------------------------------------------
// Launch
// ---------------------------------------------------------------------------
extern "C" void kernel_launch(void* const* d_in, const int* in_sizes, int n_in,
                              void* d_out, int out_size)
{
    const float* x    = (const float*)d_in[0];
    const int* mk     = (const int*)d_in[1];     // bool delivered as int32
    const float* Wq   = (const float*)d_in[2];
    const float* Wkv  = (const float*)d_in[3];
    const float* Wlin = (const float*)d_in[4];
    const float* blin = (const float*)d_in[5];
    float* out        = (float*)d_out;

    void *pqkv, *ppart, *patt, *pxs, *pctxs, *pwqkv, *pwlins;
    cudaGetSymbolAddress(&pqkv, g_qkv);
    cudaGetSymbolAddress(&ppart, g_part);
    cudaGetSymbolAddress(&patt, g_att);
    cudaGetSymbolAddress(&pxs, g_xs);
    cudaGetSymbolAddress(&pctxs, g_ctxs);
    cudaGetSymbolAddress(&pwqkv, g_wqkv);
    cudaGetSymbolAddress(&pwlins, g_wlins);
    float* qkv  = (float*)pqkv;
    float* part = (float*)ppart;
    __nv_bfloat16* att   = (__nv_bfloat16*)patt;
    __nv_bfloat16* xs    = (__nv_bfloat16*)pxs;
    __nv_bfloat16* ctxs  = (__nv_bfloat16*)pctxs;
    __nv_bfloat16* wqkv  = (__nv_bfloat16*)pwqkv;
    __nv_bfloat16* wlins = (__nv_bfloat16*)pwlins;

    const int gemm_smem = NSTG * STGB;   // 61440
    cudaFuncSetAttribute(gemm_mma, cudaFuncAttributeMaxDynamicSharedMemorySize, gemm_smem);
    cudaFuncSetAttribute(attn_mma, cudaFuncAttributeMaxDynamicSharedMemorySize, AT_SMEM);

    // one fused split for all pre-GEMM conversions
    {
        const int total = NX + NQ + NKV2 + NL;
        split_all<<<(total + 255) / 256, 256>>>(x, Wq, Wkv, Wlin, xs, wqkv, wlins);
    }

    // fused Q+KV projection: 4096 x 1536 (full K, gridDim.z = 1, 48 k-tiles)
    {
        dim3 grid(1536 / 128, NTOK / 128, 1);
        gemm_mma<<<grid, 256, gemm_smem>>>(xs, wqkv, qkv, 1536, nullptr, GK / KT);
    }
    // RoPE + split to bf16 planes
    rope_split<<<NTOK, 256>>>(qkv, att);

    // MMA attention (split-band, 8 warps, pre-split operands)
    {
        dim3 grid(TT / 64, HH, BB);
        attn_mma<<<grid, 256, AT_SMEM>>>(att, mk, ctxs);
    }

    // output projection: split-K = 2 into partials (24 k-tiles each), combine
    {
        dim3 grid(DM / 128, NTOK / 128, 2);
        gemm_mma<<<grid, 256, gemm_smem>>>(ctxs, wlins, part, DM, nullptr, GK / KT / 2);
        combine_k<<<(NTOK * DM / 4 + 255) / 256, 256>>>(part, blin, out);
    }
}